// round 8
// baseline (speedup 1.0000x reference)
#include <cuda_runtime.h>
#include <cstdint>

// CostVolume: out[b, dy*9+dx, y, x] = leaky( mean_c( c1[b,c,y,x] * warped[b,c,y+dy-4,x+dx-4] ) )
// B=8, C=192, H=128, W=160, 81 offsets.
// Round 8: 8 x-pixels/thread (tile 32x8), warp w == dy, all-FFMA2 (even dx direct,
// odd dx via reversed pairs), cp.async ping-pong, bank-safe pads (36/44),
// fused smem arena, 2-slot packed staging descriptors.

#define SR 4
#define C_TOTAL 192
#define H_TOTAL 128
#define W_TOTAL 160
#define B_TOTAL 8

#define TW 32
#define TH 8
#define NWARP 9
#define NTHREADS (NWARP * 32)     // 288
#define CC 2
#define NCHUNK (C_TOTAL / CC)     // 96
#define HH 16                     // TH + 2*SR
#define C1PAD 36                  // words; ≡4 mod 32 → conflict-free for 2-row phases
#define WPAD 44                   // words; ≡12 mod 32 → conflict-free

#define C1_WORDS (CC * TH * C1PAD)             // 576
#define BUF_WORDS (C1_WORDS + CC * HH * WPAD)  // 576 + 1408 = 1984
#define BUF_BYTES (BUF_WORDS * 4)              // 7936

#define C1_SLOTS (CC * TH * 8)        // 128
#define W_SLOTS  (CC * HH * 10)       // 320
#define TOT_SLOTS (C1_SLOTS + W_SLOTS) // 448

#define FMA2(d, a, b) \
    asm volatile("fma.rn.f32x2 %0, %1, %2, %0;" : "+l"(d) : "l"(a), "l"(b))
#define PACK2(d, lo, hi) \
    asm volatile("mov.b64 %0, {%1, %2};" : "=l"(d) : "f"(lo), "f"(hi))
#define UNPACK2(lo, hi, v) \
    asm volatile("mov.b64 {%0, %1}, %2;" : "=f"(lo), "=f"(hi) : "l"(v))
#define CP16(smem_a, gptr, sz) \
    asm volatile("cp.async.cg.shared.global [%0], [%1], 16, %2;" \
                 :: "r"(smem_a), "l"(gptr), "r"(sz))
#define CP_COMMIT() asm volatile("cp.async.commit_group;")
#define CP_WAIT(n)  asm volatile("cp.async.wait_group %0;" :: "n"(n))

__device__ __forceinline__ uint32_t smem_u32(const void* p) {
    uint32_t a;
    asm("{ .reg .u64 t; cvta.to.shared.u64 t, %1; cvt.u32.u64 %0, t; }" : "=r"(a) : "l"(p));
    return a;
}

__global__ __launch_bounds__(NTHREADS, 2)
void costvol_kernel(const float* __restrict__ c1,
                    const float* __restrict__ warped,
                    const float* __restrict__ alpha,
                    float* __restrict__ out) {
    __shared__ __align__(16) float s_all[2][BUF_WORDS];   // 15.5 KB total

    const int tid  = threadIdx.x;
    const int lane = tid & 31;
    const int dy   = tid >> 5;          // warp id == dy (0..8)
    const int xg   = lane & 3;          // 4 x-groups of 8 px
    const int row  = lane >> 2;         // pixel row 0..7
    const int tx0  = xg * 8;
    const int x0   = blockIdx.x * TW;
    const int y0   = blockIdx.y * TH;
    const int b    = blockIdx.z;

    const size_t plane = (size_t)H_TOTAL * W_TOTAL;
    const float* c1b = c1     + (size_t)b * C_TOTAL * plane;
    const float* wb  = warped + (size_t)b * C_TOTAL * plane;
    const float  av  = alpha[0];
    const size_t CHSTEP = (size_t)CC * plane;

    const uint32_t sbase = smem_u32(&s_all[0][0]);

    // ---- staging descriptors: 2 slots/thread; dst word-addr | sz-flag(bit0) ----
    const float* src[2];
    uint32_t     dstw[2];
    #pragma unroll
    for (int i = 0; i < 2; i++) {
        int j = tid + i * NTHREADS;
        if (j < C1_SLOTS) {
            int c   = j >> 6;               // 64 slots per channel
            int rem = j & 63;
            int r   = rem >> 3;
            int sl  = rem & 7;
            src[i]  = c1b + (size_t)c * plane + (size_t)(y0 + r) * W_TOTAL + (x0 + sl * 4);
            dstw[i] = (uint32_t)(((c * TH + r) * C1PAD + sl * 4) * 4) | 1u;
        } else if (j < TOT_SLOTS) {
            int h   = j - C1_SLOTS;
            int c   = h / (HH * 10);
            int rem = h - c * (HH * 10);
            int r   = rem / 10;
            int k   = rem - r * 10;
            int gy  = y0 + r - SR;
            int gx  = x0 - SR + 4 * k;
            bool ok = ((unsigned)gy < (unsigned)H_TOTAL) &&
                      ((unsigned)gx <= (unsigned)(W_TOTAL - 4));
            src[i]  = ok ? (wb + (size_t)c * plane + (size_t)gy * W_TOTAL + gx) : wb;
            dstw[i] = (uint32_t)((C1_WORDS + (c * HH + r) * WPAD + 4 * k) * 4) | (ok ? 1u : 0u);
        } else {
            // inactive: dump 16B of zeros into never-read pad (w row0 cols 40-43)
            src[i]  = wb;
            dstw[i] = (uint32_t)((C1_WORDS + 40) * 4);
        }
    }

    // ---- accumulators: even dx (acc_e) + odd-dx cross (acc_c), 40 u64 ----
    unsigned long long acc_e[5][4], acc_c[5][4];
    #pragma unroll
    for (int k = 0; k < 5; k++)
        #pragma unroll
        for (int q = 0; q < 4; q++) { acc_e[k][q] = 0ull; acc_c[k][q] = 0ull; }

    // ---- prologue: chunk 0 -> buffer 0 ----
    #pragma unroll
    for (int i = 0; i < 2; i++) {
        CP16(sbase + (dstw[i] & ~15u), src[i], (int)(dstw[i] & 1u) * 16);
        src[i] += CHSTEP;
    }
    CP_COMMIT();

    #pragma unroll 1
    for (int ch = 0; ch < NCHUNK; ch++) {
        const int cur = ch & 1;
        if (ch + 1 < NCHUNK) {
            const uint32_t nbb = sbase + ((ch + 1) & 1) * BUF_BYTES;
            #pragma unroll
            for (int i = 0; i < 2; i++) {
                CP16(nbb + (dstw[i] & ~15u), src[i], (int)(dstw[i] & 1u) * 16);
                src[i] += CHSTEP;
            }
            CP_COMMIT();
            CP_WAIT(1);
        } else {
            CP_WAIT(0);
        }
        __syncthreads();

        const float* buf = &s_all[cur][0];
        #pragma unroll 1
        for (int c = 0; c < CC; c++) {
            const float* c1row = buf + (c * TH + row) * C1PAD + tx0;
            const float* wrow  = buf + C1_WORDS + (c * HH + row + dy) * WPAD + tx0;

            const ulonglong2 av0 = *(const ulonglong2*)(c1row);
            const ulonglong2 av1 = *(const ulonglong2*)(c1row + 4);
            const ulonglong2 wv0 = *(const ulonglong2*)(wrow);
            const ulonglong2 wv1 = *(const ulonglong2*)(wrow + 4);
            const ulonglong2 wv2 = *(const ulonglong2*)(wrow + 8);
            const ulonglong2 wv3 = *(const ulonglong2*)(wrow + 12);

            const unsigned long long A[4] = {av0.x, av0.y, av1.x, av1.y};
            const unsigned long long P[8] = {wv0.x, wv0.y, wv1.x, wv1.y,
                                             wv2.x, wv2.y, wv3.x, wv3.y};
            unsigned long long R[4];
            #pragma unroll
            for (int q = 0; q < 4; q++) {
                float lo, hi;
                UNPACK2(lo, hi, A[q]);
                PACK2(R[q], hi, lo);
            }
            #pragma unroll
            for (int k = 0; k < 5; k++)
                #pragma unroll
                for (int q = 0; q < 4; q++) {
                    FMA2(acc_e[k][q], A[q], P[q + k]);
                    FMA2(acc_c[k][q], R[q], P[q + k]);
                }
        }
        __syncthreads();
    }

    // ---- epilogue: route, mean, leaky-relu, 2x ST.128 per dx ----
    const float inv = 1.0f / (float)C_TOTAL;
    float* ob = out + (size_t)b * 81 * plane + (size_t)(dy * 9) * plane
                    + (size_t)(y0 + row) * W_TOTAL + (x0 + tx0);

    float e_lo[5][4], e_hi[5][4], c_lo[5][4], c_hi[5][4];
    #pragma unroll
    for (int k = 0; k < 5; k++)
        #pragma unroll
        for (int q = 0; q < 4; q++) {
            UNPACK2(e_lo[k][q], e_hi[k][q], acc_e[k][q]);
            UNPACK2(c_lo[k][q], c_hi[k][q], acc_c[k][q]);
        }

    #pragma unroll
    for (int dx = 0; dx < 9; dx++) {
        float r[8];
        if ((dx & 1) == 0) {
            int k = dx >> 1;
            #pragma unroll
            for (int q = 0; q < 4; q++) {
                r[2 * q]     = e_lo[k][q];   // px 2q
                r[2 * q + 1] = e_hi[k][q];   // px 2q+1
            }
        } else {
            int k = dx >> 1;                 // dx = 2k+1
            #pragma unroll
            for (int q = 0; q < 4; q++) {
                r[2 * q]     = c_hi[k][q];       // px 2q,   dx=2k+1
                r[2 * q + 1] = c_lo[k + 1][q];   // px 2q+1, dx=2(k+1)-1
            }
        }
        #pragma unroll
        for (int i = 0; i < 8; i++) {
            float v = r[i] * inv;
            r[i] = (v >= 0.f) ? v : av * v;
        }
        float* o = ob + (size_t)dx * plane;
        *(float4*)(o)     = make_float4(r[0], r[1], r[2], r[3]);
        *(float4*)(o + 4) = make_float4(r[4], r[5], r[6], r[7]);
    }
}

extern "C" void kernel_launch(void* const* d_in, const int* in_sizes, int n_in,
                              void* d_out, int out_size) {
    const float* c1     = (const float*)d_in[0];
    const float* warped = (const float*)d_in[1];
    const float* alpha  = (const float*)d_in[2];
    float* out          = (float*)d_out;

    cudaFuncSetAttribute(costvol_kernel,
                         cudaFuncAttributePreferredSharedMemoryCarveout, 100);

    dim3 grid(W_TOTAL / TW, H_TOTAL / TH, B_TOTAL);   // (5, 16, 8) = 640 blocks
    dim3 block(NTHREADS);
    costvol_kernel<<<grid, block>>>(c1, warped, alpha, out);
}

// round 9
// speedup vs baseline: 1.3546x; 1.3546x over previous
#include <cuda_runtime.h>
#include <cstdint>

// CostVolume: out[b, dy*9+dx, y, x] = leaky( mean_c( c1[b,c,y,x] * warped[b,c,y+dy-4,x+dx-4] ) )
// B=8, C=192, H=128, W=160, 81 offsets.
// Round 9: 8 x-pixels/thread, warp w == dy, all-FFMA2 (even direct / odd reversed),
// cp.async ping-pong, ONE block per SM (no reg cap -> no spills), bank-safe pads.

#define SR 4
#define C_TOTAL 192
#define H_TOTAL 128
#define W_TOTAL 160
#define B_TOTAL 8

#define TW 32
#define TH 8
#define NWARP 9
#define NTHREADS (NWARP * 32)     // 288
#define CC 4
#define NCHUNK (C_TOTAL / CC)     // 48
#define HH 16                     // TH + 2*SR
#define C1PAD 36                  // stride mod 32 = 4  -> conflict-free phases
#define WPAD 44                   // stride mod 32 = 12 -> conflict-free phases

#define C1_WORDS (CC * TH * C1PAD)             // 1152
#define BUF_WORDS (C1_WORDS + CC * HH * WPAD)  // 1152 + 2816 = 3968
#define BUF_BYTES (BUF_WORDS * 4)

#define C1_SLOTS (CC * TH * 8)         // 256
#define W_SLOTS  (CC * HH * 10)        // 640
#define TOT_SLOTS (C1_SLOTS + W_SLOTS) // 896  (<= 4*288 = 1152)

#define FMA2(d, a, b) \
    asm volatile("fma.rn.f32x2 %0, %1, %2, %0;" : "+l"(d) : "l"(a), "l"(b))
#define PACK2(d, lo, hi) \
    asm volatile("mov.b64 %0, {%1, %2};" : "=l"(d) : "f"(lo), "f"(hi))
#define UNPACK2(lo, hi, v) \
    asm volatile("mov.b64 {%0, %1}, %2;" : "=f"(lo), "=f"(hi) : "l"(v))
#define CP16(smem_a, gptr, sz) \
    asm volatile("cp.async.cg.shared.global [%0], [%1], 16, %2;" \
                 :: "r"(smem_a), "l"(gptr), "r"(sz))
#define CP_COMMIT() asm volatile("cp.async.commit_group;")
#define CP_WAIT(n)  asm volatile("cp.async.wait_group %0;" :: "n"(n))

__device__ __forceinline__ uint32_t smem_u32(const void* p) {
    uint32_t a;
    asm("{ .reg .u64 t; cvta.to.shared.u64 t, %1; cvt.u32.u64 %0, t; }" : "=r"(a) : "l"(p));
    return a;
}

__global__ __launch_bounds__(NTHREADS, 1)
void costvol_kernel(const float* __restrict__ c1,
                    const float* __restrict__ warped,
                    const float* __restrict__ alpha,
                    float* __restrict__ out) {
    __shared__ __align__(16) float s_all[2][BUF_WORDS];   // 31.7 KB

    const int tid  = threadIdx.x;
    const int lane = tid & 31;
    const int dy   = tid >> 5;          // warp id == dy (0..8)
    const int xg   = lane & 3;          // 4 x-groups of 8 px
    const int row  = lane >> 2;         // pixel row 0..7
    const int tx0  = xg * 8;
    const int x0   = blockIdx.x * TW;
    const int y0   = blockIdx.y * TH;
    const int b    = blockIdx.z;

    const size_t plane = (size_t)H_TOTAL * W_TOTAL;
    const float* c1b = c1     + (size_t)b * C_TOTAL * plane;
    const float* wb  = warped + (size_t)b * C_TOTAL * plane;
    const float  av  = alpha[0];
    const size_t CHSTEP = (size_t)CC * plane;

    const uint32_t sbase = smem_u32(&s_all[0][0]);

    // ---- staging descriptors: 4 slots/thread; dst byte-addr | active-flag(bit0) ----
    const float* src[4];
    uint32_t     dstw[4];
    #pragma unroll
    for (int i = 0; i < 4; i++) {
        int j = tid + i * NTHREADS;
        if (j < C1_SLOTS) {
            int c   = j >> 6;               // 64 float4 slots per channel
            int rem = j & 63;
            int r   = rem >> 3;
            int sl  = rem & 7;
            src[i]  = c1b + (size_t)c * plane + (size_t)(y0 + r) * W_TOTAL + (x0 + sl * 4);
            dstw[i] = (uint32_t)(((c * TH + r) * C1PAD + sl * 4) * 4) | 1u;
        } else if (j < TOT_SLOTS) {
            int h   = j - C1_SLOTS;
            int c   = h / (HH * 10);
            int rem = h - c * (HH * 10);
            int r   = rem / 10;
            int k   = rem - r * 10;
            int gy  = y0 + r - SR;
            int gx  = x0 - SR + 4 * k;
            bool ok = ((unsigned)gy < (unsigned)H_TOTAL) &&
                      ((unsigned)gx <= (unsigned)(W_TOTAL - 4));
            src[i]  = ok ? (wb + (size_t)c * plane + (size_t)gy * W_TOTAL + gx) : wb;
            dstw[i] = (uint32_t)((C1_WORDS + (c * HH + r) * WPAD + 4 * k) * 4) | (ok ? 1u : 0u);
        } else {
            // inactive slot: zero-size copy into never-read c1 pad (row0 words 32..35)
            src[i]  = wb;
            dstw[i] = (uint32_t)(32 * 4);
        }
    }

    // ---- accumulators: 40 packed u64 ----
    unsigned long long acc_e[5][4], acc_c[5][4];
    #pragma unroll
    for (int k = 0; k < 5; k++)
        #pragma unroll
        for (int q = 0; q < 4; q++) { acc_e[k][q] = 0ull; acc_c[k][q] = 0ull; }

    // ---- prologue: chunk 0 -> buffer 0 ----
    #pragma unroll
    for (int i = 0; i < 4; i++) {
        CP16(sbase + (dstw[i] & ~15u), src[i], (int)(dstw[i] & 1u) * 16);
        src[i] += CHSTEP;
    }
    CP_COMMIT();

    #pragma unroll 1
    for (int ch = 0; ch < NCHUNK; ch++) {
        const int cur = ch & 1;
        if (ch + 1 < NCHUNK) {
            const uint32_t nbb = sbase + ((ch + 1) & 1) * BUF_BYTES;
            #pragma unroll
            for (int i = 0; i < 4; i++) {
                CP16(nbb + (dstw[i] & ~15u), src[i], (int)(dstw[i] & 1u) * 16);
                src[i] += CHSTEP;
            }
            CP_COMMIT();
            CP_WAIT(1);
        } else {
            CP_WAIT(0);
        }
        __syncthreads();

        const float* buf = &s_all[cur][0];
        #pragma unroll 1
        for (int c = 0; c < CC; c++) {
            const float* c1row = buf + (c * TH + row) * C1PAD + tx0;
            const float* wrow  = buf + C1_WORDS + (c * HH + row + dy) * WPAD + tx0;

            const ulonglong2 av0 = *(const ulonglong2*)(c1row);
            const ulonglong2 av1 = *(const ulonglong2*)(c1row + 4);
            const ulonglong2 wv0 = *(const ulonglong2*)(wrow);
            const ulonglong2 wv1 = *(const ulonglong2*)(wrow + 4);
            const ulonglong2 wv2 = *(const ulonglong2*)(wrow + 8);
            const ulonglong2 wv3 = *(const ulonglong2*)(wrow + 12);

            const unsigned long long A[4] = {av0.x, av0.y, av1.x, av1.y};
            const unsigned long long P[8] = {wv0.x, wv0.y, wv1.x, wv1.y,
                                             wv2.x, wv2.y, wv3.x, wv3.y};
            unsigned long long R[4];
            #pragma unroll
            for (int q = 0; q < 4; q++) {
                float lo, hi;
                UNPACK2(lo, hi, A[q]);
                PACK2(R[q], hi, lo);
            }
            #pragma unroll
            for (int k = 0; k < 5; k++)
                #pragma unroll
                for (int q = 0; q < 4; q++) {
                    FMA2(acc_e[k][q], A[q], P[q + k]);
                    FMA2(acc_c[k][q], R[q], P[q + k]);
                }
        }
        __syncthreads();
    }

    // ---- epilogue: route, mean, leaky-relu, 2x ST.128 per dx ----
    const float inv = 1.0f / (float)C_TOTAL;
    float* ob = out + (size_t)b * 81 * plane + (size_t)(dy * 9) * plane
                    + (size_t)(y0 + row) * W_TOTAL + (x0 + tx0);

    float e_lo[5][4], e_hi[5][4], c_lo[5][4], c_hi[5][4];
    #pragma unroll
    for (int k = 0; k < 5; k++)
        #pragma unroll
        for (int q = 0; q < 4; q++) {
            UNPACK2(e_lo[k][q], e_hi[k][q], acc_e[k][q]);
            UNPACK2(c_lo[k][q], c_hi[k][q], acc_c[k][q]);
        }

    #pragma unroll
    for (int dx = 0; dx < 9; dx++) {
        float r[8];
        if ((dx & 1) == 0) {
            int k = dx >> 1;
            #pragma unroll
            for (int q = 0; q < 4; q++) {
                r[2 * q]     = e_lo[k][q];       // px 2q
                r[2 * q + 1] = e_hi[k][q];       // px 2q+1
            }
        } else {
            int k = dx >> 1;                     // dx = 2k+1
            #pragma unroll
            for (int q = 0; q < 4; q++) {
                r[2 * q]     = c_hi[k][q];       // px 2q,   dx=2k+1
                r[2 * q + 1] = c_lo[k + 1][q];   // px 2q+1, dx=2(k+1)-1
            }
        }
        #pragma unroll
        for (int i = 0; i < 8; i++) {
            float v = r[i] * inv;
            r[i] = (v >= 0.f) ? v : av * v;
        }
        float* o = ob + (size_t)dx * plane;
        *(float4*)(o)     = make_float4(r[0], r[1], r[2], r[3]);
        *(float4*)(o + 4) = make_float4(r[4], r[5], r[6], r[7]);
    }
}

extern "C" void kernel_launch(void* const* d_in, const int* in_sizes, int n_in,
                              void* d_out, int out_size) {
    const float* c1     = (const float*)d_in[0];
    const float* warped = (const float*)d_in[1];
    const float* alpha  = (const float*)d_in[2];
    float* out          = (float*)d_out;

    cudaFuncSetAttribute(costvol_kernel,
                         cudaFuncAttributePreferredSharedMemoryCarveout, 100);

    dim3 grid(W_TOTAL / TW, H_TOTAL / TH, B_TOTAL);   // (5, 16, 8) = 640 blocks
    dim3 block(NTHREADS);
    costvol_kernel<<<grid, block>>>(c1, warped, alpha, out);
}

// round 10
// speedup vs baseline: 1.9599x; 1.4468x over previous
#include <cuda_runtime.h>
#include <cstdint>

// CostVolume: out[b, dy*9+dx, y, x] = leaky( mean_c( c1[b,c,y,x] * warped[b,c,y+dy-4,x+dx-4] ) )
// B=8, C=192, H=128, W=160, 81 offsets.
// Round 10: R7 math (4 px/thread, warp==dy, FFMA2 even/odd-reversed) at 3 blocks/SM
// (27 warps). Triple-buffered smem ring -> ONE barrier per chunk. Packed staging
// descriptors for register economy.

#define SR 4
#define C_TOTAL 192
#define H_TOTAL 128
#define W_TOTAL 160
#define B_TOTAL 8

#define TW 32
#define TH 4
#define NWARP 9
#define NTHREADS (NWARP * 32)     // 288
#define CC 4
#define NCHUNK (C_TOTAL / CC)     // 48
#define HH 12                     // TH + 2*SR
#define WPAD 48

#define C1_WORDS (CC * TH * TW)                // 512
#define BUF_WORDS (C1_WORDS + CC * HH * WPAD)  // 512 + 2304 = 2816
#define BUF_BYTES (BUF_WORDS * 4)              // 11264

#define C1_SLOTS (CC * TH * 8)         // 128
#define W_SLOTS  (CC * HH * 10)        // 480
#define TOT_SLOTS (C1_SLOTS + W_SLOTS) // 608

#define FMA2(d, a, b) \
    asm volatile("fma.rn.f32x2 %0, %1, %2, %0;" : "+l"(d) : "l"(a), "l"(b))
#define PACK2(d, lo, hi) \
    asm volatile("mov.b64 %0, {%1, %2};" : "=l"(d) : "f"(lo), "f"(hi))
#define UNPACK2(lo, hi, v) \
    asm volatile("mov.b64 {%0, %1}, %2;" : "=f"(lo), "=f"(hi) : "l"(v))
#define CP16(smem_a, gptr, sz) \
    asm volatile("cp.async.cg.shared.global [%0], [%1], 16, %2;" \
                 :: "r"(smem_a), "l"(gptr), "r"(sz))
#define CP_COMMIT() asm volatile("cp.async.commit_group;")
#define CP_WAIT(n)  asm volatile("cp.async.wait_group %0;" :: "n"(n))

__device__ __forceinline__ uint32_t smem_u32(const void* p) {
    uint32_t a;
    asm("{ .reg .u64 t; cvta.to.shared.u64 t, %1; cvt.u32.u64 %0, t; }" : "=r"(a) : "l"(p));
    return a;
}

__global__ __launch_bounds__(NTHREADS, 3)
void costvol_kernel(const float* __restrict__ c1,
                    const float* __restrict__ warped,
                    const float* __restrict__ alpha,
                    float* __restrict__ out) {
    __shared__ __align__(16) float s_all[3][BUF_WORDS];   // 33.8 KB

    const int tid  = threadIdx.x;
    const int lane = tid & 31;
    const int dy   = tid >> 5;          // warp id == dy (0..8)
    const int xg   = lane & 7;          // 8 x-groups of 4 px
    const int row  = lane >> 3;         // pixel row 0..3
    const int tx0  = xg * 4;
    const int x0   = blockIdx.x * TW;
    const int y0   = blockIdx.y * TH;
    const int b    = blockIdx.z;

    const size_t plane = (size_t)H_TOTAL * W_TOTAL;
    const float* c1b = c1     + (size_t)b * C_TOTAL * plane;
    const float* wb  = warped + (size_t)b * C_TOTAL * plane;
    const float  av  = alpha[0];
    const size_t CHSTEP = (size_t)CC * plane;

    const uint32_t sbase = smem_u32(&s_all[0][0]);

    // ---- staging descriptors: 3 slots/thread; dst byte-addr | active(bit0) ----
    const float* src[3];
    uint32_t     dstw[3];
    #pragma unroll
    for (int i = 0; i < 3; i++) {
        int j = tid + i * NTHREADS;
        if (j < C1_SLOTS) {
            int c   = j >> 5;               // 32 float4 slots per channel
            int rem = j & 31;
            int r   = rem >> 3;
            int sl  = rem & 7;
            src[i]  = c1b + (size_t)c * plane + (size_t)(y0 + r) * W_TOTAL + (x0 + sl * 4);
            dstw[i] = (uint32_t)(((c * TH + r) * TW + sl * 4) * 4) | 1u;
        } else if (j < TOT_SLOTS) {
            int h   = j - C1_SLOTS;
            int c   = h / (HH * 10);
            int rem = h - c * (HH * 10);
            int r   = rem / 10;
            int k   = rem - r * 10;
            int gy  = y0 + r - SR;
            int gx  = x0 - SR + 4 * k;
            bool ok = ((unsigned)gy < (unsigned)H_TOTAL) &&
                      ((unsigned)gx <= (unsigned)(W_TOTAL - 4));
            src[i]  = ok ? (wb + (size_t)c * plane + (size_t)gy * W_TOTAL + gx) : wb;
            dstw[i] = (uint32_t)((C1_WORDS + (c * HH + r) * WPAD + 4 * k) * 4) | (ok ? 1u : 0u);
        } else {
            // inactive: zero-size copy into never-read halo pad (cols 40..43 of row 0)
            src[i]  = wb;
            dstw[i] = (uint32_t)((C1_WORDS + 40) * 4);
        }
    }

    // ---- accumulators: 20 packed u64 ----
    unsigned long long acc_e[5][2], acc_c[5][2];
    #pragma unroll
    for (int k = 0; k < 5; k++) {
        acc_e[k][0] = 0ull; acc_e[k][1] = 0ull;
        acc_c[k][0] = 0ull; acc_c[k][1] = 0ull;
    }

    // ---- prologue: chunk 0 -> ring buffer 0 ----
    #pragma unroll
    for (int i = 0; i < 3; i++) {
        CP16(sbase + (dstw[i] & ~15u), src[i], (int)(dstw[i] & 1u) * 16);
        src[i] += CHSTEP;
    }
    CP_COMMIT();

    uint32_t curoff = 0, nxtoff = BUF_BYTES;   // ring offsets (mod 3*BUF_BYTES)

    #pragma unroll 1
    for (int ch = 0; ch < NCHUNK; ch++) {
        if (ch + 1 < NCHUNK) {
            #pragma unroll
            for (int i = 0; i < 3; i++) {
                CP16(sbase + nxtoff + (dstw[i] & ~15u), src[i], (int)(dstw[i] & 1u) * 16);
                src[i] += CHSTEP;
            }
            CP_COMMIT();
            CP_WAIT(1);
        } else {
            CP_WAIT(0);
        }
        __syncthreads();   // single barrier per chunk (ring depth 3 makes tail-sync redundant)

        const float* buf = (const float*)((const char*)&s_all[0][0] + curoff);
        #pragma unroll
        for (int c = 0; c < CC; c++) {
            const float* c1row = buf + (c * TH + row) * TW + tx0;
            const float* wrow  = buf + C1_WORDS + (c * HH + row + dy) * WPAD + tx0;

            const ulonglong2 avv = *(const ulonglong2*)(c1row);
            const ulonglong2 wv0 = *(const ulonglong2*)(wrow);
            const ulonglong2 wv1 = *(const ulonglong2*)(wrow + 4);
            const ulonglong2 wv2 = *(const ulonglong2*)(wrow + 8);
            const unsigned long long P[6] = {wv0.x, wv0.y, wv1.x, wv1.y, wv2.x, wv2.y};

            float a0, a1, a2, a3;
            UNPACK2(a0, a1, avv.x);
            UNPACK2(a2, a3, avv.y);
            unsigned long long rev01, rev23;
            PACK2(rev01, a1, a0);
            PACK2(rev23, a3, a2);

            #pragma unroll
            for (int k = 0; k < 5; k++) {
                FMA2(acc_e[k][0], avv.x, P[k]);
                FMA2(acc_e[k][1], avv.y, P[k + 1]);
                FMA2(acc_c[k][0], rev01, P[k]);
                FMA2(acc_c[k][1], rev23, P[k + 1]);
            }
        }

        // advance ring
        curoff = nxtoff;
        nxtoff += BUF_BYTES;
        if (nxtoff == 3 * BUF_BYTES) nxtoff = 0;
    }

    // ---- epilogue: route, mean, leaky-relu, ST.128 ----
    const float inv = 1.0f / (float)C_TOTAL;
    float* ob = out + (size_t)b * 81 * plane + (size_t)(dy * 9) * plane
                    + (size_t)(y0 + row) * W_TOTAL + (x0 + tx0);

    float e_lo[5][2], e_hi[5][2], c_lo[5][2], c_hi[5][2];
    #pragma unroll
    for (int k = 0; k < 5; k++) {
        UNPACK2(e_lo[k][0], e_hi[k][0], acc_e[k][0]);
        UNPACK2(e_lo[k][1], e_hi[k][1], acc_e[k][1]);
        UNPACK2(c_lo[k][0], c_hi[k][0], acc_c[k][0]);
        UNPACK2(c_lo[k][1], c_hi[k][1], acc_c[k][1]);
    }

    #pragma unroll
    for (int dx = 0; dx < 9; dx++) {
        float r0, r1, r2, r3;
        if ((dx & 1) == 0) {
            int k = dx >> 1;
            r0 = e_lo[k][0]; r1 = e_hi[k][0];
            r2 = e_lo[k][1]; r3 = e_hi[k][1];
        } else {
            int k = dx >> 1;              // dx = 2k+1
            r0 = c_hi[k][0];              // px0 dx=2k+1
            r1 = c_lo[k + 1][0];          // px1 dx=2(k+1)-1
            r2 = c_hi[k][1];
            r3 = c_lo[k + 1][1];
        }
        r0 *= inv; r1 *= inv; r2 *= inv; r3 *= inv;
        float4 v;
        v.x = (r0 >= 0.f) ? r0 : av * r0;
        v.y = (r1 >= 0.f) ? r1 : av * r1;
        v.z = (r2 >= 0.f) ? r2 : av * r2;
        v.w = (r3 >= 0.f) ? r3 : av * r3;
        *(float4*)(ob + (size_t)dx * plane) = v;
    }
}

extern "C" void kernel_launch(void* const* d_in, const int* in_sizes, int n_in,
                              void* d_out, int out_size) {
    const float* c1     = (const float*)d_in[0];
    const float* warped = (const float*)d_in[1];
    const float* alpha  = (const float*)d_in[2];
    float* out          = (float*)d_out;

    cudaFuncSetAttribute(costvol_kernel,
                         cudaFuncAttributePreferredSharedMemoryCarveout, 100);

    dim3 grid(W_TOTAL / TW, H_TOTAL / TH, B_TOTAL);   // (5, 32, 8) = 1280
    dim3 block(NTHREADS);
    costvol_kernel<<<grid, block>>>(c1, warped, alpha, out);
}

// round 11
// speedup vs baseline: 1.9756x; 1.0081x over previous
#include <cuda_runtime.h>
#include <cstdint>

// CostVolume: out[b, dy*9+dx, y, x] = leaky( mean_c( c1[b,c,y,x] * warped[b,c,y+dy-4,x+dx-4] ) )
// B=8, C=192, H=128, W=160, 81 offsets.
// Round 10: R7 math (4 px/thread, warp==dy, FFMA2 even/odd-reversed) at 3 blocks/SM
// (27 warps). Triple-buffered smem ring -> ONE barrier per chunk. Packed staging
// descriptors for register economy.

#define SR 4
#define C_TOTAL 192
#define H_TOTAL 128
#define W_TOTAL 160
#define B_TOTAL 8

#define TW 32
#define TH 4
#define NWARP 9
#define NTHREADS (NWARP * 32)     // 288
#define CC 4
#define NCHUNK (C_TOTAL / CC)     // 48
#define HH 12                     // TH + 2*SR
#define WPAD 48

#define C1_WORDS (CC * TH * TW)                // 512
#define BUF_WORDS (C1_WORDS + CC * HH * WPAD)  // 512 + 2304 = 2816
#define BUF_BYTES (BUF_WORDS * 4)              // 11264

#define C1_SLOTS (CC * TH * 8)         // 128
#define W_SLOTS  (CC * HH * 10)        // 480
#define TOT_SLOTS (C1_SLOTS + W_SLOTS) // 608

#define FMA2(d, a, b) \
    asm volatile("fma.rn.f32x2 %0, %1, %2, %0;" : "+l"(d) : "l"(a), "l"(b))
#define PACK2(d, lo, hi) \
    asm volatile("mov.b64 %0, {%1, %2};" : "=l"(d) : "f"(lo), "f"(hi))
#define UNPACK2(lo, hi, v) \
    asm volatile("mov.b64 {%0, %1}, %2;" : "=f"(lo), "=f"(hi) : "l"(v))
#define CP16(smem_a, gptr, sz) \
    asm volatile("cp.async.cg.shared.global [%0], [%1], 16, %2;" \
                 :: "r"(smem_a), "l"(gptr), "r"(sz))
#define CP_COMMIT() asm volatile("cp.async.commit_group;")
#define CP_WAIT(n)  asm volatile("cp.async.wait_group %0;" :: "n"(n))

__device__ __forceinline__ uint32_t smem_u32(const void* p) {
    uint32_t a;
    asm("{ .reg .u64 t; cvta.to.shared.u64 t, %1; cvt.u32.u64 %0, t; }" : "=r"(a) : "l"(p));
    return a;
}

__global__ __launch_bounds__(NTHREADS, 3)
void costvol_kernel(const float* __restrict__ c1,
                    const float* __restrict__ warped,
                    const float* __restrict__ alpha,
                    float* __restrict__ out) {
    __shared__ __align__(16) float s_all[3][BUF_WORDS];   // 33.8 KB

    const int tid  = threadIdx.x;
    const int lane = tid & 31;
    const int dy   = tid >> 5;          // warp id == dy (0..8)
    const int xg   = lane & 7;          // 8 x-groups of 4 px
    const int row  = lane >> 3;         // pixel row 0..3
    const int tx0  = xg * 4;
    const int x0   = blockIdx.x * TW;
    const int y0   = blockIdx.y * TH;
    const int b    = blockIdx.z;

    const size_t plane = (size_t)H_TOTAL * W_TOTAL;
    const float* c1b = c1     + (size_t)b * C_TOTAL * plane;
    const float* wb  = warped + (size_t)b * C_TOTAL * plane;
    const float  av  = alpha[0];
    const size_t CHSTEP = (size_t)CC * plane;

    const uint32_t sbase = smem_u32(&s_all[0][0]);

    // ---- staging descriptors: 3 slots/thread; dst byte-addr | active(bit0) ----
    const float* src[3];
    uint32_t     dstw[3];
    #pragma unroll
    for (int i = 0; i < 3; i++) {
        int j = tid + i * NTHREADS;
        if (j < C1_SLOTS) {
            int c   = j >> 5;               // 32 float4 slots per channel
            int rem = j & 31;
            int r   = rem >> 3;
            int sl  = rem & 7;
            src[i]  = c1b + (size_t)c * plane + (size_t)(y0 + r) * W_TOTAL + (x0 + sl * 4);
            dstw[i] = (uint32_t)(((c * TH + r) * TW + sl * 4) * 4) | 1u;
        } else if (j < TOT_SLOTS) {
            int h   = j - C1_SLOTS;
            int c   = h / (HH * 10);
            int rem = h - c * (HH * 10);
            int r   = rem / 10;
            int k   = rem - r * 10;
            int gy  = y0 + r - SR;
            int gx  = x0 - SR + 4 * k;
            bool ok = ((unsigned)gy < (unsigned)H_TOTAL) &&
                      ((unsigned)gx <= (unsigned)(W_TOTAL - 4));
            src[i]  = ok ? (wb + (size_t)c * plane + (size_t)gy * W_TOTAL + gx) : wb;
            dstw[i] = (uint32_t)((C1_WORDS + (c * HH + r) * WPAD + 4 * k) * 4) | (ok ? 1u : 0u);
        } else {
            // inactive: zero-size copy into never-read halo pad (cols 40..43 of row 0)
            src[i]  = wb;
            dstw[i] = (uint32_t)((C1_WORDS + 40) * 4);
        }
    }

    // ---- accumulators: 20 packed u64 ----
    unsigned long long acc_e[5][2], acc_c[5][2];
    #pragma unroll
    for (int k = 0; k < 5; k++) {
        acc_e[k][0] = 0ull; acc_e[k][1] = 0ull;
        acc_c[k][0] = 0ull; acc_c[k][1] = 0ull;
    }

    // ---- prologue: chunk 0 -> ring buffer 0 ----
    #pragma unroll
    for (int i = 0; i < 3; i++) {
        CP16(sbase + (dstw[i] & ~15u), src[i], (int)(dstw[i] & 1u) * 16);
        src[i] += CHSTEP;
    }
    CP_COMMIT();

    uint32_t curoff = 0, nxtoff = BUF_BYTES;   // ring offsets (mod 3*BUF_BYTES)

    #pragma unroll 1
    for (int ch = 0; ch < NCHUNK; ch++) {
        if (ch + 1 < NCHUNK) {
            #pragma unroll
            for (int i = 0; i < 3; i++) {
                CP16(sbase + nxtoff + (dstw[i] & ~15u), src[i], (int)(dstw[i] & 1u) * 16);
                src[i] += CHSTEP;
            }
            CP_COMMIT();
            CP_WAIT(1);
        } else {
            CP_WAIT(0);
        }
        __syncthreads();   // single barrier per chunk (ring depth 3 makes tail-sync redundant)

        const float* buf = (const float*)((const char*)&s_all[0][0] + curoff);
        #pragma unroll
        for (int c = 0; c < CC; c++) {
            const float* c1row = buf + (c * TH + row) * TW + tx0;
            const float* wrow  = buf + C1_WORDS + (c * HH + row + dy) * WPAD + tx0;

            const ulonglong2 avv = *(const ulonglong2*)(c1row);
            const ulonglong2 wv0 = *(const ulonglong2*)(wrow);
            const ulonglong2 wv1 = *(const ulonglong2*)(wrow + 4);
            const ulonglong2 wv2 = *(const ulonglong2*)(wrow + 8);
            const unsigned long long P[6] = {wv0.x, wv0.y, wv1.x, wv1.y, wv2.x, wv2.y};

            float a0, a1, a2, a3;
            UNPACK2(a0, a1, avv.x);
            UNPACK2(a2, a3, avv.y);
            unsigned long long rev01, rev23;
            PACK2(rev01, a1, a0);
            PACK2(rev23, a3, a2);

            #pragma unroll
            for (int k = 0; k < 5; k++) {
                FMA2(acc_e[k][0], avv.x, P[k]);
                FMA2(acc_e[k][1], avv.y, P[k + 1]);
                FMA2(acc_c[k][0], rev01, P[k]);
                FMA2(acc_c[k][1], rev23, P[k + 1]);
            }
        }

        // advance ring
        curoff = nxtoff;
        nxtoff += BUF_BYTES;
        if (nxtoff == 3 * BUF_BYTES) nxtoff = 0;
    }

    // ---- epilogue: route, mean, leaky-relu, ST.128 ----
    const float inv = 1.0f / (float)C_TOTAL;
    float* ob = out + (size_t)b * 81 * plane + (size_t)(dy * 9) * plane
                    + (size_t)(y0 + row) * W_TOTAL + (x0 + tx0);

    float e_lo[5][2], e_hi[5][2], c_lo[5][2], c_hi[5][2];
    #pragma unroll
    for (int k = 0; k < 5; k++) {
        UNPACK2(e_lo[k][0], e_hi[k][0], acc_e[k][0]);
        UNPACK2(e_lo[k][1], e_hi[k][1], acc_e[k][1]);
        UNPACK2(c_lo[k][0], c_hi[k][0], acc_c[k][0]);
        UNPACK2(c_lo[k][1], c_hi[k][1], acc_c[k][1]);
    }

    #pragma unroll
    for (int dx = 0; dx < 9; dx++) {
        float r0, r1, r2, r3;
        if ((dx & 1) == 0) {
            int k = dx >> 1;
            r0 = e_lo[k][0]; r1 = e_hi[k][0];
            r2 = e_lo[k][1]; r3 = e_hi[k][1];
        } else {
            int k = dx >> 1;              // dx = 2k+1
            r0 = c_hi[k][0];              // px0 dx=2k+1
            r1 = c_lo[k + 1][0];          // px1 dx=2(k+1)-1
            r2 = c_hi[k][1];
            r3 = c_lo[k + 1][1];
        }
        r0 *= inv; r1 *= inv; r2 *= inv; r3 *= inv;
        float4 v;
        v.x = (r0 >= 0.f) ? r0 : av * r0;
        v.y = (r1 >= 0.f) ? r1 : av * r1;
        v.z = (r2 >= 0.f) ? r2 : av * r2;
        v.w = (r3 >= 0.f) ? r3 : av * r3;
        *(float4*)(ob + (size_t)dx * plane) = v;
    }
}

extern "C" void kernel_launch(void* const* d_in, const int* in_sizes, int n_in,
                              void* d_out, int out_size) {
    const float* c1     = (const float*)d_in[0];
    const float* warped = (const float*)d_in[1];
    const float* alpha  = (const float*)d_in[2];
    float* out          = (float*)d_out;

    cudaFuncSetAttribute(costvol_kernel,
                         cudaFuncAttributePreferredSharedMemoryCarveout, 100);

    dim3 grid(W_TOTAL / TW, H_TOTAL / TH, B_TOTAL);   // (5, 32, 8) = 1280
    dim3 block(NTHREADS);
    costvol_kernel<<<grid, block>>>(c1, warped, alpha, out);
}

// round 12
// speedup vs baseline: 2.0040x; 1.0144x over previous
#include <cuda_runtime.h>
#include <cstdint>

// CostVolume: out[b, dy*9+dx, y, x] = leaky( mean_c( c1[b,c,y,x] * warped[b,c,y+dy-4,x+dx-4] ) )
// B=8, C=192, H=128, W=160, 81 offsets.
// Round 11: anti-diagonal pairing. Thread-unit computes outputs (y0, dy) and
// (y0+1, dy-1) which SHARE window row s=y0+dy: per channel 5 LDS.128 feed
// 40 FFMA2 (was 8 for the same work). 20 units x 8 xg = 160 threads,
// cp.async ring-3, all-FFMA2 even/odd-reversed scheme, 3 blocks/SM (no spill).

#define SR 4
#define C_TOTAL 192
#define H_TOTAL 128
#define W_TOTAL 160
#define B_TOTAL 8

#define TW 32
#define TH 4
#define NUNIT 20
#define NTHREADS (NUNIT * 8)      // 160
#define CC 2
#define NCHUNK (C_TOTAL / CC)     // 96
#define HH 12                     // TH + 2*SR
#define WPAD 44

#define C1_WORDS (CC * TH * TW)                // 256
#define BUF_WORDS (C1_WORDS + CC * HH * WPAD)  // 256 + 1056 = 1312
#define BUF_BYTES (BUF_WORDS * 4)              // 5248

#define C1_SLOTS (CC * TH * 8)         // 64
#define W_SLOTS  (CC * HH * 10)        // 240
#define TOT_SLOTS (C1_SLOTS + W_SLOTS) // 304

// unit tables: window row s, first output row y0, pair flag (second output valid)
__constant__ unsigned char u_s[NUNIT] = {0,1,2,2,3,3,4,4,5,5,6,6,7,7,8,8,9,9,10,11};
__constant__ unsigned char u_y[NUNIT] = {0,0,0,2,0,2,0,2,0,2,0,2,0,2,0,2,1,3,2,3};
__constant__ unsigned char u_p[NUNIT] = {0,1,1,0,1,1,1,1,1,1,1,1,1,1,1,1,1,0,1,0};

#define FMA2(d, a, b) \
    asm volatile("fma.rn.f32x2 %0, %1, %2, %0;" : "+l"(d) : "l"(a), "l"(b))
#define PACK2(d, lo, hi) \
    asm volatile("mov.b64 %0, {%1, %2};" : "=l"(d) : "f"(lo), "f"(hi))
#define UNPACK2(lo, hi, v) \
    asm volatile("mov.b64 {%0, %1}, %2;" : "=f"(lo), "=f"(hi) : "l"(v))
#define CP16(smem_a, gptr, sz) \
    asm volatile("cp.async.cg.shared.global [%0], [%1], 16, %2;" \
                 :: "r"(smem_a), "l"(gptr), "r"(sz))
#define CP_COMMIT() asm volatile("cp.async.commit_group;")
#define CP_WAIT(n)  asm volatile("cp.async.wait_group %0;" :: "n"(n))

__device__ __forceinline__ uint32_t smem_u32(const void* p) {
    uint32_t a;
    asm("{ .reg .u64 t; cvta.to.shared.u64 t, %1; cvt.u32.u64 %0, t; }" : "=r"(a) : "l"(p));
    return a;
}

__global__ __launch_bounds__(NTHREADS, 3)
void costvol_kernel(const float* __restrict__ c1,
                    const float* __restrict__ warped,
                    const float* __restrict__ alpha,
                    float* __restrict__ out) {
    __shared__ __align__(16) float s_all[3][BUF_WORDS];   // 15.7 KB

    const int tid = threadIdx.x;
    const int xg  = tid & 7;            // x-group: 4 px each
    const int u   = tid >> 3;           // unit 0..19
    const int tx0 = xg * 4;
    const int x0  = blockIdx.x * TW;
    const int y0t = blockIdx.y * TH;
    const int b   = blockIdx.z;

    const int s   = u_s[u];             // shared window row
    const int ya  = u_y[u];             // first output pixel row
    const int pr  = u_p[u];             // second output valid
    const int yb  = (ya + 1 < TH) ? (ya + 1) : (TH - 1);  // clamped (padded units)
    const int dy1 = s - ya;             // dy of first output (in [0,9))
    const int dy2 = dy1 - 1;            // dy of second output (valid iff pr)

    const size_t plane = (size_t)H_TOTAL * W_TOTAL;
    const float* c1b = c1     + (size_t)b * C_TOTAL * plane;
    const float* wb  = warped + (size_t)b * C_TOTAL * plane;
    const float  av  = alpha[0];
    const size_t CHSTEP = (size_t)CC * plane;

    const uint32_t sbase = smem_u32(&s_all[0][0]);

    // ---- staging descriptors: 2 slots/thread; dst byte-addr | active(bit0) ----
    const float* src[2];
    uint32_t     dstw[2];
    #pragma unroll
    for (int i = 0; i < 2; i++) {
        int j = tid + i * NTHREADS;
        if (j < C1_SLOTS) {
            int c   = j >> 5;               // 32 float4 slots per channel
            int rem = j & 31;
            int r   = rem >> 3;
            int sl  = rem & 7;
            src[i]  = c1b + (size_t)c * plane + (size_t)(y0t + r) * W_TOTAL + (x0 + sl * 4);
            dstw[i] = (uint32_t)(((c * TH + r) * TW + sl * 4) * 4) | 1u;
        } else if (j < TOT_SLOTS) {
            int h   = j - C1_SLOTS;
            int c   = h / (HH * 10);
            int rem = h - c * (HH * 10);
            int r   = rem / 10;
            int k   = rem - r * 10;
            int gy  = y0t + r - SR;
            int gx  = x0 - SR + 4 * k;
            bool ok = ((unsigned)gy < (unsigned)H_TOTAL) &&
                      ((unsigned)gx <= (unsigned)(W_TOTAL - 4));
            src[i]  = ok ? (wb + (size_t)c * plane + (size_t)gy * W_TOTAL + gx) : wb;
            dstw[i] = (uint32_t)((C1_WORDS + (c * HH + r) * WPAD + 4 * k) * 4) | (ok ? 1u : 0u);
        } else {
            // inactive: zero-size copy into never-read halo pad
            src[i]  = wb;
            dstw[i] = (uint32_t)((C1_WORDS + 40) * 4);
        }
    }

    // ---- accumulators: two outputs x (even + cross) x 5k x 2 px-groups = 40 u64 ----
    unsigned long long Ae[5][2], Ac[5][2];   // output A: (ya, dy1)
    unsigned long long Be[5][2], Bc[5][2];   // output B: (yb, dy2)
    #pragma unroll
    for (int k = 0; k < 5; k++) {
        Ae[k][0] = 0ull; Ae[k][1] = 0ull; Ac[k][0] = 0ull; Ac[k][1] = 0ull;
        Be[k][0] = 0ull; Be[k][1] = 0ull; Bc[k][0] = 0ull; Bc[k][1] = 0ull;
    }

    // ---- prologue: chunk 0 -> ring buffer 0 ----
    #pragma unroll
    for (int i = 0; i < 2; i++) {
        CP16(sbase + (dstw[i] & ~15u), src[i], (int)(dstw[i] & 1u) * 16);
        src[i] += CHSTEP;
    }
    CP_COMMIT();

    uint32_t curoff = 0, nxtoff = BUF_BYTES;

    #pragma unroll 1
    for (int ch = 0; ch < NCHUNK; ch++) {
        if (ch + 1 < NCHUNK) {
            #pragma unroll
            for (int i = 0; i < 2; i++) {
                CP16(sbase + nxtoff + (dstw[i] & ~15u), src[i], (int)(dstw[i] & 1u) * 16);
                src[i] += CHSTEP;
            }
            CP_COMMIT();
            CP_WAIT(1);
        } else {
            CP_WAIT(0);
        }
        __syncthreads();   // single barrier per chunk (ring depth 3)

        const float* buf = (const float*)((const char*)&s_all[0][0] + curoff);
        #pragma unroll
        for (int c = 0; c < CC; c++) {
            const float* wrow = buf + C1_WORDS + (c * HH + s) * WPAD + tx0;
            const ulonglong2 wv0 = *(const ulonglong2*)(wrow);
            const ulonglong2 wv1 = *(const ulonglong2*)(wrow + 4);
            const ulonglong2 wv2 = *(const ulonglong2*)(wrow + 8);
            const unsigned long long P[6] = {wv0.x, wv0.y, wv1.x, wv1.y, wv2.x, wv2.y};

            const ulonglong2 a1v = *(const ulonglong2*)(buf + (c * TH + ya) * TW + tx0);
            const ulonglong2 a2v = *(const ulonglong2*)(buf + (c * TH + yb) * TW + tx0);

            float f0, f1, f2, f3;
            unsigned long long r1x, r1y, r2x, r2y;
            UNPACK2(f0, f1, a1v.x);  PACK2(r1x, f1, f0);
            UNPACK2(f2, f3, a1v.y);  PACK2(r1y, f3, f2);
            UNPACK2(f0, f1, a2v.x);  PACK2(r2x, f1, f0);
            UNPACK2(f2, f3, a2v.y);  PACK2(r2y, f3, f2);

            #pragma unroll
            for (int k = 0; k < 5; k++) {
                FMA2(Ae[k][0], a1v.x, P[k]);
                FMA2(Ae[k][1], a1v.y, P[k + 1]);
                FMA2(Ac[k][0], r1x,   P[k]);
                FMA2(Ac[k][1], r1y,   P[k + 1]);
                FMA2(Be[k][0], a2v.x, P[k]);
                FMA2(Be[k][1], a2v.y, P[k + 1]);
                FMA2(Bc[k][0], r2x,   P[k]);
                FMA2(Bc[k][1], r2y,   P[k + 1]);
            }
        }

        curoff = nxtoff;
        nxtoff += BUF_BYTES;
        if (nxtoff == 3 * BUF_BYTES) nxtoff = 0;
    }

    // ---- epilogue: route, mean, leaky-relu, ST.128 ----
    const float inv = 1.0f / (float)C_TOTAL;

    // output A: (row ya, dy1)
    {
        float e_lo[5][2], e_hi[5][2], c_lo[5][2], c_hi[5][2];
        #pragma unroll
        for (int k = 0; k < 5; k++) {
            UNPACK2(e_lo[k][0], e_hi[k][0], Ae[k][0]);
            UNPACK2(e_lo[k][1], e_hi[k][1], Ae[k][1]);
            UNPACK2(c_lo[k][0], c_hi[k][0], Ac[k][0]);
            UNPACK2(c_lo[k][1], c_hi[k][1], Ac[k][1]);
        }
        float* ob = out + (size_t)b * 81 * plane + (size_t)(dy1 * 9) * plane
                        + (size_t)(y0t + ya) * W_TOTAL + (x0 + tx0);
        #pragma unroll
        for (int dx = 0; dx < 9; dx++) {
            float r0, r1, r2, r3;
            if ((dx & 1) == 0) {
                int k = dx >> 1;
                r0 = e_lo[k][0]; r1 = e_hi[k][0]; r2 = e_lo[k][1]; r3 = e_hi[k][1];
            } else {
                int k = dx >> 1;
                r0 = c_hi[k][0]; r1 = c_lo[k + 1][0]; r2 = c_hi[k][1]; r3 = c_lo[k + 1][1];
            }
            r0 *= inv; r1 *= inv; r2 *= inv; r3 *= inv;
            float4 v;
            v.x = (r0 >= 0.f) ? r0 : av * r0;
            v.y = (r1 >= 0.f) ? r1 : av * r1;
            v.z = (r2 >= 0.f) ? r2 : av * r2;
            v.w = (r3 >= 0.f) ? r3 : av * r3;
            *(float4*)(ob + (size_t)dx * plane) = v;
        }
    }

    // output B: (row yb, dy2) — only for pair units
    if (pr) {
        float e_lo[5][2], e_hi[5][2], c_lo[5][2], c_hi[5][2];
        #pragma unroll
        for (int k = 0; k < 5; k++) {
            UNPACK2(e_lo[k][0], e_hi[k][0], Be[k][0]);
            UNPACK2(e_lo[k][1], e_hi[k][1], Be[k][1]);
            UNPACK2(c_lo[k][0], c_hi[k][0], Bc[k][0]);
            UNPACK2(c_lo[k][1], c_hi[k][1], Bc[k][1]);
        }
        float* ob = out + (size_t)b * 81 * plane + (size_t)(dy2 * 9) * plane
                        + (size_t)(y0t + yb) * W_TOTAL + (x0 + tx0);
        #pragma unroll
        for (int dx = 0; dx < 9; dx++) {
            float r0, r1, r2, r3;
            if ((dx & 1) == 0) {
                int k = dx >> 1;
                r0 = e_lo[k][0]; r1 = e_hi[k][0]; r2 = e_lo[k][1]; r3 = e_hi[k][1];
            } else {
                int k = dx >> 1;
                r0 = c_hi[k][0]; r1 = c_lo[k + 1][0]; r2 = c_hi[k][1]; r3 = c_lo[k + 1][1];
            }
            r0 *= inv; r1 *= inv; r2 *= inv; r3 *= inv;
            float4 v;
            v.x = (r0 >= 0.f) ? r0 : av * r0;
            v.y = (r1 >= 0.f) ? r1 : av * r1;
            v.z = (r2 >= 0.f) ? r2 : av * r2;
            v.w = (r3 >= 0.f) ? r3 : av * r3;
            *(float4*)(ob + (size_t)dx * plane) = v;
        }
    }
}

extern "C" void kernel_launch(void* const* d_in, const int* in_sizes, int n_in,
                              void* d_out, int out_size) {
    const float* c1     = (const float*)d_in[0];
    const float* warped = (const float*)d_in[1];
    const float* alpha  = (const float*)d_in[2];
    float* out          = (float*)d_out;

    cudaFuncSetAttribute(costvol_kernel,
                         cudaFuncAttributePreferredSharedMemoryCarveout, 100);

    dim3 grid(W_TOTAL / TW, H_TOTAL / TH, B_TOTAL);   // (5, 32, 8) = 1280
    dim3 block(NTHREADS);                              // 160
    costvol_kernel<<<grid, block>>>(c1, warped, alpha, out);
}

// round 13
// speedup vs baseline: 2.4114x; 1.2033x over previous
#include <cuda_runtime.h>
#include <cstdint>

// CostVolume: out[b, dy*9+dx, y, x] = leaky( mean_c( c1[b,c,y,x] * warped[b,c,y+dy-4,x+dx-4] ) )
// B=8, C=192, H=128, W=160, 81 offsets.
// Round 12: R11 anti-diagonal pairing +
//  - singles packed into warp 0 (warp-uniform pr) -> zero ghost FMAs/loads
//  - CC=4 (48 barriers instead of 96, deeper channel pipelining)

#define SR 4
#define C_TOTAL 192
#define H_TOTAL 128
#define W_TOTAL 160
#define B_TOTAL 8

#define TW 32
#define TH 4
#define NUNIT 20
#define NTHREADS (NUNIT * 8)      // 160
#define CC 4
#define NCHUNK (C_TOTAL / CC)     // 48
#define HH 12                     // TH + 2*SR
#define WPAD 44

#define C1_WORDS (CC * TH * TW)                // 512
#define BUF_WORDS (C1_WORDS + CC * HH * WPAD)  // 512 + 2112 = 2624
#define BUF_BYTES (BUF_WORDS * 4)              // 10496

#define C1_SLOTS (CC * TH * 8)         // 128
#define W_SLOTS  (CC * HH * 10)        // 480
#define TOT_SLOTS (C1_SLOTS + W_SLOTS) // 608

// unit tables, singles (pr=0) packed into units 0..3 == warp 0.
// pairs: output A=(ya, s-ya), output B=(ya+1, s-ya-1).
__constant__ unsigned char u_s[NUNIT] = {0,2,9,11, 1,2,3,3,4,4,5,5,6,6,7,7,8,8,9,10};
__constant__ unsigned char u_y[NUNIT] = {0,2,3,3,  0,0,0,2,0,2,0,2,0,2,0,2,0,2,1,2};
__constant__ unsigned char u_p[NUNIT] = {0,0,0,0,  1,1,1,1,1,1,1,1,1,1,1,1,1,1,1,1};

#define FMA2(d, a, b) \
    asm volatile("fma.rn.f32x2 %0, %1, %2, %0;" : "+l"(d) : "l"(a), "l"(b))
#define PACK2(d, lo, hi) \
    asm volatile("mov.b64 %0, {%1, %2};" : "=l"(d) : "f"(lo), "f"(hi))
#define UNPACK2(lo, hi, v) \
    asm volatile("mov.b64 {%0, %1}, %2;" : "=f"(lo), "=f"(hi) : "l"(v))
#define CP16(smem_a, gptr, sz) \
    asm volatile("cp.async.cg.shared.global [%0], [%1], 16, %2;" \
                 :: "r"(smem_a), "l"(gptr), "r"(sz))
#define CP_COMMIT() asm volatile("cp.async.commit_group;")
#define CP_WAIT(n)  asm volatile("cp.async.wait_group %0;" :: "n"(n))

__device__ __forceinline__ uint32_t smem_u32(const void* p) {
    uint32_t a;
    asm("{ .reg .u64 t; cvta.to.shared.u64 t, %1; cvt.u32.u64 %0, t; }" : "=r"(a) : "l"(p));
    return a;
}

__global__ __launch_bounds__(NTHREADS, 3)
void costvol_kernel(const float* __restrict__ c1,
                    const float* __restrict__ warped,
                    const float* __restrict__ alpha,
                    float* __restrict__ out) {
    __shared__ __align__(16) float s_all[3][BUF_WORDS];   // 31.5 KB

    const int tid = threadIdx.x;
    const int xg  = tid & 7;            // x-group: 4 px each
    const int u   = tid >> 3;           // unit 0..19
    const int tx0 = xg * 4;
    const int x0  = blockIdx.x * TW;
    const int y0t = blockIdx.y * TH;
    const int b   = blockIdx.z;

    const int s   = u_s[u];             // shared window row
    const int ya  = u_y[u];             // first output pixel row
    const int pr  = u_p[u];             // pair flag (warp-uniform: warp0 = 0)
    const int yb  = (ya + 1 < TH) ? (ya + 1) : (TH - 1);
    const int dy1 = s - ya;
    const int dy2 = dy1 - 1;

    const size_t plane = (size_t)H_TOTAL * W_TOTAL;
    const float* c1b = c1     + (size_t)b * C_TOTAL * plane;
    const float* wb  = warped + (size_t)b * C_TOTAL * plane;
    const float  av  = alpha[0];
    const size_t CHSTEP = (size_t)CC * plane;

    const uint32_t sbase = smem_u32(&s_all[0][0]);

    // ---- staging descriptors: 4 slots/thread; dst byte-addr | active(bit0) ----
    const float* src[4];
    uint32_t     dstw[4];
    #pragma unroll
    for (int i = 0; i < 4; i++) {
        int j = tid + i * NTHREADS;
        if (j < C1_SLOTS) {
            int c   = j >> 5;               // 32 float4 slots per channel
            int rem = j & 31;
            int r   = rem >> 3;
            int sl  = rem & 7;
            src[i]  = c1b + (size_t)c * plane + (size_t)(y0t + r) * W_TOTAL + (x0 + sl * 4);
            dstw[i] = (uint32_t)(((c * TH + r) * TW + sl * 4) * 4) | 1u;
        } else if (j < TOT_SLOTS) {
            int h   = j - C1_SLOTS;
            int c   = h / (HH * 10);
            int rem = h - c * (HH * 10);
            int r   = rem / 10;
            int k   = rem - r * 10;
            int gy  = y0t + r - SR;
            int gx  = x0 - SR + 4 * k;
            bool ok = ((unsigned)gy < (unsigned)H_TOTAL) &&
                      ((unsigned)gx <= (unsigned)(W_TOTAL - 4));
            src[i]  = ok ? (wb + (size_t)c * plane + (size_t)gy * W_TOTAL + gx) : wb;
            dstw[i] = (uint32_t)((C1_WORDS + (c * HH + r) * WPAD + 4 * k) * 4) | (ok ? 1u : 0u);
        } else {
            // inactive: zero-size copy into never-read halo pad
            src[i]  = wb;
            dstw[i] = (uint32_t)((C1_WORDS + 40) * 4);
        }
    }

    // ---- accumulators ----
    unsigned long long Ae[5][2], Ac[5][2];   // output A: (ya, dy1)
    unsigned long long Be[5][2], Bc[5][2];   // output B: (yb, dy2), pairs only
    #pragma unroll
    for (int k = 0; k < 5; k++) {
        Ae[k][0] = 0ull; Ae[k][1] = 0ull; Ac[k][0] = 0ull; Ac[k][1] = 0ull;
        Be[k][0] = 0ull; Be[k][1] = 0ull; Bc[k][0] = 0ull; Bc[k][1] = 0ull;
    }

    // ---- prologue: chunk 0 -> ring buffer 0 ----
    #pragma unroll
    for (int i = 0; i < 4; i++) {
        CP16(sbase + (dstw[i] & ~15u), src[i], (int)(dstw[i] & 1u) * 16);
        src[i] += CHSTEP;
    }
    CP_COMMIT();

    uint32_t curoff = 0, nxtoff = BUF_BYTES;

    #pragma unroll 1
    for (int ch = 0; ch < NCHUNK; ch++) {
        if (ch + 1 < NCHUNK) {
            #pragma unroll
            for (int i = 0; i < 4; i++) {
                CP16(sbase + nxtoff + (dstw[i] & ~15u), src[i], (int)(dstw[i] & 1u) * 16);
                src[i] += CHSTEP;
            }
            CP_COMMIT();
            CP_WAIT(1);
        } else {
            CP_WAIT(0);
        }
        __syncthreads();   // single barrier per chunk (ring depth 3)

        const float* buf = (const float*)((const char*)&s_all[0][0] + curoff);
        #pragma unroll
        for (int c = 0; c < CC; c++) {
            const float* wrow = buf + C1_WORDS + (c * HH + s) * WPAD + tx0;
            const ulonglong2 wv0 = *(const ulonglong2*)(wrow);
            const ulonglong2 wv1 = *(const ulonglong2*)(wrow + 4);
            const ulonglong2 wv2 = *(const ulonglong2*)(wrow + 8);
            const unsigned long long P[6] = {wv0.x, wv0.y, wv1.x, wv1.y, wv2.x, wv2.y};

            const ulonglong2 a1v = *(const ulonglong2*)(buf + (c * TH + ya) * TW + tx0);

            float f0, f1, f2, f3;
            unsigned long long r1x, r1y;
            UNPACK2(f0, f1, a1v.x);  PACK2(r1x, f1, f0);
            UNPACK2(f2, f3, a1v.y);  PACK2(r1y, f3, f2);

            #pragma unroll
            for (int k = 0; k < 5; k++) {
                FMA2(Ae[k][0], a1v.x, P[k]);
                FMA2(Ae[k][1], a1v.y, P[k + 1]);
                FMA2(Ac[k][0], r1x,   P[k]);
                FMA2(Ac[k][1], r1y,   P[k + 1]);
            }

            if (pr) {   // warp-uniform: warp 0 skips the whole B side
                const ulonglong2 a2v = *(const ulonglong2*)(buf + (c * TH + yb) * TW + tx0);
                unsigned long long r2x, r2y;
                UNPACK2(f0, f1, a2v.x);  PACK2(r2x, f1, f0);
                UNPACK2(f2, f3, a2v.y);  PACK2(r2y, f3, f2);
                #pragma unroll
                for (int k = 0; k < 5; k++) {
                    FMA2(Be[k][0], a2v.x, P[k]);
                    FMA2(Be[k][1], a2v.y, P[k + 1]);
                    FMA2(Bc[k][0], r2x,   P[k]);
                    FMA2(Bc[k][1], r2y,   P[k + 1]);
                }
            }
        }

        curoff = nxtoff;
        nxtoff += BUF_BYTES;
        if (nxtoff == 3 * BUF_BYTES) nxtoff = 0;
    }

    // ---- epilogue: route, mean, leaky-relu, ST.128 ----
    const float inv = 1.0f / (float)C_TOTAL;

    // output A: (row ya, dy1)
    {
        float e_lo[5][2], e_hi[5][2], c_lo[5][2], c_hi[5][2];
        #pragma unroll
        for (int k = 0; k < 5; k++) {
            UNPACK2(e_lo[k][0], e_hi[k][0], Ae[k][0]);
            UNPACK2(e_lo[k][1], e_hi[k][1], Ae[k][1]);
            UNPACK2(c_lo[k][0], c_hi[k][0], Ac[k][0]);
            UNPACK2(c_lo[k][1], c_hi[k][1], Ac[k][1]);
        }
        float* ob = out + (size_t)b * 81 * plane + (size_t)(dy1 * 9) * plane
                        + (size_t)(y0t + ya) * W_TOTAL + (x0 + tx0);
        #pragma unroll
        for (int dx = 0; dx < 9; dx++) {
            float r0, r1, r2, r3;
            if ((dx & 1) == 0) {
                int k = dx >> 1;
                r0 = e_lo[k][0]; r1 = e_hi[k][0]; r2 = e_lo[k][1]; r3 = e_hi[k][1];
            } else {
                int k = dx >> 1;
                r0 = c_hi[k][0]; r1 = c_lo[k + 1][0]; r2 = c_hi[k][1]; r3 = c_lo[k + 1][1];
            }
            r0 *= inv; r1 *= inv; r2 *= inv; r3 *= inv;
            float4 v;
            v.x = (r0 >= 0.f) ? r0 : av * r0;
            v.y = (r1 >= 0.f) ? r1 : av * r1;
            v.z = (r2 >= 0.f) ? r2 : av * r2;
            v.w = (r3 >= 0.f) ? r3 : av * r3;
            *(float4*)(ob + (size_t)dx * plane) = v;
        }
    }

    // output B: (row yb, dy2) — pairs only (warp-uniform)
    if (pr) {
        float e_lo[5][2], e_hi[5][2], c_lo[5][2], c_hi[5][2];
        #pragma unroll
        for (int k = 0; k < 5; k++) {
            UNPACK2(e_lo[k][0], e_hi[k][0], Be[k][0]);
            UNPACK2(e_lo[k][1], e_hi[k][1], Be[k][1]);
            UNPACK2(c_lo[k][0], c_hi[k][0], Bc[k][0]);
            UNPACK2(c_lo[k][1], c_hi[k][1], Bc[k][1]);
        }
        float* ob = out + (size_t)b * 81 * plane + (size_t)(dy2 * 9) * plane
                        + (size_t)(y0t + yb) * W_TOTAL + (x0 + tx0);
        #pragma unroll
        for (int dx = 0; dx < 9; dx++) {
            float r0, r1, r2, r3;
            if ((dx & 1) == 0) {
                int k = dx >> 1;
                r0 = e_lo[k][0]; r1 = e_hi[k][0]; r2 = e_lo[k][1]; r3 = e_hi[k][1];
            } else {
                int k = dx >> 1;
                r0 = c_hi[k][0]; r1 = c_lo[k + 1][0]; r2 = c_hi[k][1]; r3 = c_lo[k + 1][1];
            }
            r0 *= inv; r1 *= inv; r2 *= inv; r3 *= inv;
            float4 v;
            v.x = (r0 >= 0.f) ? r0 : av * r0;
            v.y = (r1 >= 0.f) ? r1 : av * r1;
            v.z = (r2 >= 0.f) ? r2 : av * r2;
            v.w = (r3 >= 0.f) ? r3 : av * r3;
            *(float4*)(ob + (size_t)dx * plane) = v;
        }
    }
}

extern "C" void kernel_launch(void* const* d_in, const int* in_sizes, int n_in,
                              void* d_out, int out_size) {
    const float* c1     = (const float*)d_in[0];
    const float* warped = (const float*)d_in[1];
    const float* alpha  = (const float*)d_in[2];
    float* out          = (float*)d_out;

    cudaFuncSetAttribute(costvol_kernel,
                         cudaFuncAttributePreferredSharedMemoryCarveout, 100);

    dim3 grid(W_TOTAL / TW, H_TOTAL / TH, B_TOTAL);   // (5, 32, 8) = 1280
    dim3 block(NTHREADS);                              // 160
    costvol_kernel<<<grid, block>>>(c1, warped, alpha, out);
}

// round 14
// speedup vs baseline: 2.4257x; 1.0059x over previous
#include <cuda_runtime.h>
#include <cstdint>

// CostVolume: out[b, dy*9+dx, y, x] = leaky( mean_c( c1[b,c,y,x] * warped[b,c,y+dy-4,x+dx-4] ) )
// B=8, C=192, H=128, W=160, 81 offsets.
// Round 13: R12 + same-s warp packing. Pair cover re-chosen (ya=0: s=1..8,
// ya=2: s=3..10) so warps 1-3 hold quads with only TWO distinct window rows
// -> smem broadcast halves window crossbar cost. Singles remain in warp 0.

#define SR 4
#define C_TOTAL 192
#define H_TOTAL 128
#define W_TOTAL 160
#define B_TOTAL 8

#define TW 32
#define TH 4
#define NUNIT 20
#define NTHREADS (NUNIT * 8)      // 160
#define CC 4
#define NCHUNK (C_TOTAL / CC)     // 48
#define HH 12                     // TH + 2*SR
#define WPAD 44

#define C1_WORDS (CC * TH * TW)                // 512
#define BUF_WORDS (C1_WORDS + CC * HH * WPAD)  // 512 + 2112 = 2624
#define BUF_BYTES (BUF_WORDS * 4)              // 10496

#define C1_SLOTS (CC * TH * 8)         // 128
#define W_SLOTS  (CC * HH * 10)        // 480
#define TOT_SLOTS (C1_SLOTS + W_SLOTS) // 608

// unit tables. warp = 4 consecutive units.
// w0: singles (0,0),(1,8),(2,0),(3,8)  [pr=0, no B side]
// w1: s={3,3,4,4}  w2: s={5,5,6,6}  w3: s={7,7,8,8}  (2 distinct rows/warp)
// w4: s={1,2,9,10}
// pairs: output A=(ya, s-ya), output B=(ya+1, s-ya-1).
__constant__ unsigned char u_s[NUNIT] = {0,9,2,11, 3,3,4,4, 5,5,6,6, 7,7,8,8, 1,2,9,10};
__constant__ unsigned char u_y[NUNIT] = {0,1,2,3,  0,2,0,2, 0,2,0,2, 0,2,0,2, 0,0,2,2};
__constant__ unsigned char u_p[NUNIT] = {0,0,0,0,  1,1,1,1, 1,1,1,1, 1,1,1,1, 1,1,1,1};

#define FMA2(d, a, b) \
    asm volatile("fma.rn.f32x2 %0, %1, %2, %0;" : "+l"(d) : "l"(a), "l"(b))
#define PACK2(d, lo, hi) \
    asm volatile("mov.b64 %0, {%1, %2};" : "=l"(d) : "f"(lo), "f"(hi))
#define UNPACK2(lo, hi, v) \
    asm volatile("mov.b64 {%0, %1}, %2;" : "=f"(lo), "=f"(hi) : "l"(v))
#define CP16(smem_a, gptr, sz) \
    asm volatile("cp.async.cg.shared.global [%0], [%1], 16, %2;" \
                 :: "r"(smem_a), "l"(gptr), "r"(sz))
#define CP_COMMIT() asm volatile("cp.async.commit_group;")
#define CP_WAIT(n)  asm volatile("cp.async.wait_group %0;" :: "n"(n))

__device__ __forceinline__ uint32_t smem_u32(const void* p) {
    uint32_t a;
    asm("{ .reg .u64 t; cvta.to.shared.u64 t, %1; cvt.u32.u64 %0, t; }" : "=r"(a) : "l"(p));
    return a;
}

__global__ __launch_bounds__(NTHREADS, 3)
void costvol_kernel(const float* __restrict__ c1,
                    const float* __restrict__ warped,
                    const float* __restrict__ alpha,
                    float* __restrict__ out) {
    __shared__ __align__(16) float s_all[3][BUF_WORDS];   // 31.5 KB

    const int tid = threadIdx.x;
    const int xg  = tid & 7;            // x-group: 4 px each
    const int u   = tid >> 3;           // unit 0..19
    const int tx0 = xg * 4;
    const int x0  = blockIdx.x * TW;
    const int y0t = blockIdx.y * TH;
    const int b   = blockIdx.z;

    const int s   = u_s[u];             // shared window row
    const int ya  = u_y[u];             // first output pixel row
    const int pr  = u_p[u];             // pair flag (warp-uniform)
    const int yb  = (ya + 1 < TH) ? (ya + 1) : (TH - 1);
    const int dy1 = s - ya;
    const int dy2 = dy1 - 1;

    const size_t plane = (size_t)H_TOTAL * W_TOTAL;
    const float* c1b = c1     + (size_t)b * C_TOTAL * plane;
    const float* wb  = warped + (size_t)b * C_TOTAL * plane;
    const float  av  = alpha[0];
    const size_t CHSTEP = (size_t)CC * plane;

    const uint32_t sbase = smem_u32(&s_all[0][0]);

    // ---- staging descriptors: 4 slots/thread; dst byte-addr | active(bit0) ----
    const float* src[4];
    uint32_t     dstw[4];
    #pragma unroll
    for (int i = 0; i < 4; i++) {
        int j = tid + i * NTHREADS;
        if (j < C1_SLOTS) {
            int c   = j >> 5;               // 32 float4 slots per channel
            int rem = j & 31;
            int r   = rem >> 3;
            int sl  = rem & 7;
            src[i]  = c1b + (size_t)c * plane + (size_t)(y0t + r) * W_TOTAL + (x0 + sl * 4);
            dstw[i] = (uint32_t)(((c * TH + r) * TW + sl * 4) * 4) | 1u;
        } else if (j < TOT_SLOTS) {
            int h   = j - C1_SLOTS;
            int c   = h / (HH * 10);
            int rem = h - c * (HH * 10);
            int r   = rem / 10;
            int k   = rem - r * 10;
            int gy  = y0t + r - SR;
            int gx  = x0 - SR + 4 * k;
            bool ok = ((unsigned)gy < (unsigned)H_TOTAL) &&
                      ((unsigned)gx <= (unsigned)(W_TOTAL - 4));
            src[i]  = ok ? (wb + (size_t)c * plane + (size_t)gy * W_TOTAL + gx) : wb;
            dstw[i] = (uint32_t)((C1_WORDS + (c * HH + r) * WPAD + 4 * k) * 4) | (ok ? 1u : 0u);
        } else {
            // inactive: zero-size copy into never-read halo pad
            src[i]  = wb;
            dstw[i] = (uint32_t)((C1_WORDS + 40) * 4);
        }
    }

    // ---- accumulators ----
    unsigned long long Ae[5][2], Ac[5][2];   // output A: (ya, dy1)
    unsigned long long Be[5][2], Bc[5][2];   // output B: (yb, dy2), pairs only
    #pragma unroll
    for (int k = 0; k < 5; k++) {
        Ae[k][0] = 0ull; Ae[k][1] = 0ull; Ac[k][0] = 0ull; Ac[k][1] = 0ull;
        Be[k][0] = 0ull; Be[k][1] = 0ull; Bc[k][0] = 0ull; Bc[k][1] = 0ull;
    }

    // ---- prologue: chunk 0 -> ring buffer 0 ----
    #pragma unroll
    for (int i = 0; i < 4; i++) {
        CP16(sbase + (dstw[i] & ~15u), src[i], (int)(dstw[i] & 1u) * 16);
        src[i] += CHSTEP;
    }
    CP_COMMIT();

    uint32_t curoff = 0, nxtoff = BUF_BYTES;

    #pragma unroll 1
    for (int ch = 0; ch < NCHUNK; ch++) {
        if (ch + 1 < NCHUNK) {
            #pragma unroll
            for (int i = 0; i < 4; i++) {
                CP16(sbase + nxtoff + (dstw[i] & ~15u), src[i], (int)(dstw[i] & 1u) * 16);
                src[i] += CHSTEP;
            }
            CP_COMMIT();
            CP_WAIT(1);
        } else {
            CP_WAIT(0);
        }
        __syncthreads();   // single barrier per chunk (ring depth 3)

        const float* buf = (const float*)((const char*)&s_all[0][0] + curoff);
        #pragma unroll
        for (int c = 0; c < CC; c++) {
            const float* wrow = buf + C1_WORDS + (c * HH + s) * WPAD + tx0;
            const ulonglong2 wv0 = *(const ulonglong2*)(wrow);
            const ulonglong2 wv1 = *(const ulonglong2*)(wrow + 4);
            const ulonglong2 wv2 = *(const ulonglong2*)(wrow + 8);
            const unsigned long long P[6] = {wv0.x, wv0.y, wv1.x, wv1.y, wv2.x, wv2.y};

            const ulonglong2 a1v = *(const ulonglong2*)(buf + (c * TH + ya) * TW + tx0);

            float f0, f1, f2, f3;
            unsigned long long r1x, r1y;
            UNPACK2(f0, f1, a1v.x);  PACK2(r1x, f1, f0);
            UNPACK2(f2, f3, a1v.y);  PACK2(r1y, f3, f2);

            #pragma unroll
            for (int k = 0; k < 5; k++) {
                FMA2(Ae[k][0], a1v.x, P[k]);
                FMA2(Ae[k][1], a1v.y, P[k + 1]);
                FMA2(Ac[k][0], r1x,   P[k]);
                FMA2(Ac[k][1], r1y,   P[k + 1]);
            }

            if (pr) {   // warp-uniform: warp 0 skips the whole B side
                const ulonglong2 a2v = *(const ulonglong2*)(buf + (c * TH + yb) * TW + tx0);
                unsigned long long r2x, r2y;
                UNPACK2(f0, f1, a2v.x);  PACK2(r2x, f1, f0);
                UNPACK2(f2, f3, a2v.y);  PACK2(r2y, f3, f2);
                #pragma unroll
                for (int k = 0; k < 5; k++) {
                    FMA2(Be[k][0], a2v.x, P[k]);
                    FMA2(Be[k][1], a2v.y, P[k + 1]);
                    FMA2(Bc[k][0], r2x,   P[k]);
                    FMA2(Bc[k][1], r2y,   P[k + 1]);
                }
            }
        }

        curoff = nxtoff;
        nxtoff += BUF_BYTES;
        if (nxtoff == 3 * BUF_BYTES) nxtoff = 0;
    }

    // ---- epilogue: route, mean, leaky-relu, ST.128 ----
    const float inv = 1.0f / (float)C_TOTAL;

    // output A: (row ya, dy1)
    {
        float e_lo[5][2], e_hi[5][2], c_lo[5][2], c_hi[5][2];
        #pragma unroll
        for (int k = 0; k < 5; k++) {
            UNPACK2(e_lo[k][0], e_hi[k][0], Ae[k][0]);
            UNPACK2(e_lo[k][1], e_hi[k][1], Ae[k][1]);
            UNPACK2(c_lo[k][0], c_hi[k][0], Ac[k][0]);
            UNPACK2(c_lo[k][1], c_hi[k][1], Ac[k][1]);
        }
        float* ob = out + (size_t)b * 81 * plane + (size_t)(dy1 * 9) * plane
                        + (size_t)(y0t + ya) * W_TOTAL + (x0 + tx0);
        #pragma unroll
        for (int dx = 0; dx < 9; dx++) {
            float r0, r1, r2, r3;
            if ((dx & 1) == 0) {
                int k = dx >> 1;
                r0 = e_lo[k][0]; r1 = e_hi[k][0]; r2 = e_lo[k][1]; r3 = e_hi[k][1];
            } else {
                int k = dx >> 1;
                r0 = c_hi[k][0]; r1 = c_lo[k + 1][0]; r2 = c_hi[k][1]; r3 = c_lo[k + 1][1];
            }
            r0 *= inv; r1 *= inv; r2 *= inv; r3 *= inv;
            float4 v;
            v.x = (r0 >= 0.f) ? r0 : av * r0;
            v.y = (r1 >= 0.f) ? r1 : av * r1;
            v.z = (r2 >= 0.f) ? r2 : av * r2;
            v.w = (r3 >= 0.f) ? r3 : av * r3;
            *(float4*)(ob + (size_t)dx * plane) = v;
        }
    }

    // output B: (row yb, dy2) — pairs only (warp-uniform)
    if (pr) {
        float e_lo[5][2], e_hi[5][2], c_lo[5][2], c_hi[5][2];
        #pragma unroll
        for (int k = 0; k < 5; k++) {
            UNPACK2(e_lo[k][0], e_hi[k][0], Be[k][0]);
            UNPACK2(e_lo[k][1], e_hi[k][1], Be[k][1]);
            UNPACK2(c_lo[k][0], c_hi[k][0], Bc[k][0]);
            UNPACK2(c_lo[k][1], c_hi[k][1], Bc[k][1]);
        }
        float* ob = out + (size_t)b * 81 * plane + (size_t)(dy2 * 9) * plane
                        + (size_t)(y0t + yb) * W_TOTAL + (x0 + tx0);
        #pragma unroll
        for (int dx = 0; dx < 9; dx++) {
            float r0, r1, r2, r3;
            if ((dx & 1) == 0) {
                int k = dx >> 1;
                r0 = e_lo[k][0]; r1 = e_hi[k][0]; r2 = e_lo[k][1]; r3 = e_hi[k][1];
            } else {
                int k = dx >> 1;
                r0 = c_hi[k][0]; r1 = c_lo[k + 1][0]; r2 = c_hi[k][1]; r3 = c_lo[k + 1][1];
            }
            r0 *= inv; r1 *= inv; r2 *= inv; r3 *= inv;
            float4 v;
            v.x = (r0 >= 0.f) ? r0 : av * r0;
            v.y = (r1 >= 0.f) ? r1 : av * r1;
            v.z = (r2 >= 0.f) ? r2 : av * r2;
            v.w = (r3 >= 0.f) ? r3 : av * r3;
            *(float4*)(ob + (size_t)dx * plane) = v;
        }
    }
}

extern "C" void kernel_launch(void* const* d_in, const int* in_sizes, int n_in,
                              void* d_out, int out_size) {
    const float* c1     = (const float*)d_in[0];
    const float* warped = (const float*)d_in[1];
    const float* alpha  = (const float*)d_in[2];
    float* out          = (float*)d_out;

    cudaFuncSetAttribute(costvol_kernel,
                         cudaFuncAttributePreferredSharedMemoryCarveout, 100);

    dim3 grid(W_TOTAL / TW, H_TOTAL / TH, B_TOTAL);   // (5, 32, 8) = 1280
    dim3 block(NTHREADS);                              // 160
    costvol_kernel<<<grid, block>>>(c1, warped, alpha, out);
}